// round 1
// baseline (speedup 1.0000x reference)
#include <cuda_runtime.h>
#include <cuda_bf16.h>
#include <math.h>

// Problem constants (fixed shapes from the reference)
#define BATCH 4
#define SEQ   2048
#define DM    1024
#define HEADS 16
#define DK    64
#define BS    (BATCH * SEQ)   // 8192 rows

// ---------------- scratch (allocation-free: __device__ globals) ----------------
__device__ float g_qproj[BS * DM];     // [B,S,H*DK]  32 MB
__device__ float g_kh[BS * DK];        // [B,S,DK]     2 MB
__device__ float g_vh[BS * DK];        // [B,S,DK]     2 MB
__device__ float g_attn[BS * DM];      // [B,S,H*DK]  32 MB

// ---------------- tiled SGEMM with bias: C[M,N] = A[M,K] @ W[K,N] + bias ------
// BM/TM * BN/TN must equal 256 (threads). M%BM==0, N%BN==0, K%BK==0 assumed.
template <int BM, int BN, int BK, int TM, int TN>
__global__ __launch_bounds__(256) void sgemm_bias_kernel(
    const float* __restrict__ A, const float* __restrict__ W,
    const float* __restrict__ bias, float* __restrict__ C,
    int M, int N, int K)
{
    __shared__ float As[BK][BM];   // K-transposed A tile
    __shared__ float Bs[BK][BN];

    const int tid = threadIdx.x;
    const int tx  = tid % (BN / TN);
    const int ty  = tid / (BN / TN);
    const int rowBase = blockIdx.y * BM;
    const int colBase = blockIdx.x * BN;

    float acc[TM][TN];
#pragma unroll
    for (int i = 0; i < TM; i++)
#pragma unroll
        for (int j = 0; j < TN; j++) acc[i][j] = 0.f;

    constexpr int A_LD = (BM * BK) / (256 * 4);   // float4 loads per thread
    constexpr int B_LD = (BN * BK) / (256 * 4);

    for (int kb = 0; kb < K; kb += BK) {
        // load A tile (coalesced along K), store transposed into As
#pragma unroll
        for (int i = 0; i < A_LD; i++) {
            int l  = tid + i * 256;           // float4 index within tile
            int r  = l / (BK / 4);
            int kq = l % (BK / 4);
            float4 v = *(const float4*)&A[(size_t)(rowBase + r) * K + kb + kq * 4];
            As[kq * 4 + 0][r] = v.x;
            As[kq * 4 + 1][r] = v.y;
            As[kq * 4 + 2][r] = v.z;
            As[kq * 4 + 3][r] = v.w;
        }
        // load W tile (coalesced along N)
#pragma unroll
        for (int i = 0; i < B_LD; i++) {
            int l  = tid + i * 256;
            int r  = l / (BN / 4);
            int cq = l % (BN / 4);
            *(float4*)&Bs[r][cq * 4] =
                *(const float4*)&W[(size_t)(kb + r) * N + colBase + cq * 4];
        }
        __syncthreads();

#pragma unroll
        for (int kk = 0; kk < BK; kk++) {
            float a[TM], b[TN];
#pragma unroll
            for (int i = 0; i < TM; i += 4) {
                float4 v = *(const float4*)&As[kk][ty * TM + i];
                a[i] = v.x; a[i + 1] = v.y; a[i + 2] = v.z; a[i + 3] = v.w;
            }
#pragma unroll
            for (int j = 0; j < TN; j += 4) {
                float4 v = *(const float4*)&Bs[kk][tx * TN + j];
                b[j] = v.x; b[j + 1] = v.y; b[j + 2] = v.z; b[j + 3] = v.w;
            }
#pragma unroll
            for (int i = 0; i < TM; i++)
#pragma unroll
                for (int j = 0; j < TN; j++)
                    acc[i][j] = fmaf(a[i], b[j], acc[i][j]);
        }
        __syncthreads();
    }

    // epilogue: bias + float4 stores
#pragma unroll
    for (int i = 0; i < TM; i++) {
        int row = rowBase + ty * TM + i;
#pragma unroll
        for (int j = 0; j < TN; j += 4) {
            int col = colBase + tx * TN + j;
            float4 o;
            o.x = acc[i][j + 0] + bias[col + 0];
            o.y = acc[i][j + 1] + bias[col + 1];
            o.z = acc[i][j + 2] + bias[col + 2];
            o.w = acc[i][j + 3] + bias[col + 3];
            *(float4*)&C[(size_t)row * N + col] = o;
        }
    }
}

// ---------------- MQA flash attention (fp32, online softmax) -------------------
// One thread = one query row. Block handles BR rows for one (b, h).
// K/V head is shared across all H heads (MQA) -> heavy L2 reuse of g_kh/g_vh.
#define BR 128
#define BC 32

__global__ __launch_bounds__(BR) void mqa_attn_kernel(
    const float* __restrict__ qproj,   // [B,S,H*DK]
    const float* __restrict__ kh,      // [B,S,DK]
    const float* __restrict__ vh,      // [B,S,DK]
    float* __restrict__ attn_out)      // [B,S,H*DK]
{
    __shared__ float Ks[BC][DK];
    __shared__ float Vs[BC][DK];

    const int t  = threadIdx.x;
    const int qt = blockIdx.x;     // query tile
    const int h  = blockIdx.y;
    const int b  = blockIdx.z;
    const int row = qt * BR + t;   // sequence position of this thread's query

    const float scale = 0.125f;    // 1/sqrt(64)

    // load this thread's Q row, pre-scaled
    float q[DK];
    {
        const float* qp = qproj + ((size_t)(b * SEQ + row)) * DM + h * DK;
#pragma unroll
        for (int d = 0; d < DK; d += 4) {
            float4 v = *(const float4*)&qp[d];
            q[d + 0] = v.x * scale;
            q[d + 1] = v.y * scale;
            q[d + 2] = v.z * scale;
            q[d + 3] = v.w * scale;
        }
    }

    float O[DK];
#pragma unroll
    for (int d = 0; d < DK; d++) O[d] = 0.f;
    float m = -1e30f;
    float l = 0.f;

    for (int kt = 0; kt < SEQ; kt += BC) {
        // cooperative K/V tile load: BC*DK floats each, float4, coalesced
#pragma unroll
        for (int i = 0; i < (BC * DK) / (BR * 4); i++) {   // 4 iterations
            int l4 = t + i * BR;
            int r  = l4 / (DK / 4);
            int c  = (l4 % (DK / 4)) * 4;
            size_t g = ((size_t)(b * SEQ + kt + r)) * DK + c;
            *(float4*)&Ks[r][c] = *(const float4*)&kh[g];
            *(float4*)&Vs[r][c] = *(const float4*)&vh[g];
        }
        __syncthreads();

        // scores for this row against BC keys (K rows are warp-broadcast LDS)
        float s[BC];
#pragma unroll
        for (int j = 0; j < BC; j++) {
            const float4* kr = (const float4*)Ks[j];
            float sum = 0.f;
#pragma unroll
            for (int d4 = 0; d4 < DK / 4; d4++) {
                float4 kv = kr[d4];
                sum = fmaf(q[d4 * 4 + 0], kv.x, sum);
                sum = fmaf(q[d4 * 4 + 1], kv.y, sum);
                sum = fmaf(q[d4 * 4 + 2], kv.z, sum);
                sum = fmaf(q[d4 * 4 + 3], kv.w, sum);
            }
            s[j] = sum;
        }

        // online softmax update
        float mt = m;
#pragma unroll
        for (int j = 0; j < BC; j++) mt = fmaxf(mt, s[j]);
        float corr = __expf(m - mt);
        m = mt;
        l *= corr;
#pragma unroll
        for (int d = 0; d < DK; d++) O[d] *= corr;

#pragma unroll
        for (int j = 0; j < BC; j++) {
            float p = __expf(s[j] - m);
            l += p;
            const float4* vr = (const float4*)Vs[j];
#pragma unroll
            for (int d4 = 0; d4 < DK / 4; d4++) {
                float4 vv = vr[d4];
                O[d4 * 4 + 0] = fmaf(p, vv.x, O[d4 * 4 + 0]);
                O[d4 * 4 + 1] = fmaf(p, vv.y, O[d4 * 4 + 1]);
                O[d4 * 4 + 2] = fmaf(p, vv.z, O[d4 * 4 + 2]);
                O[d4 * 4 + 3] = fmaf(p, vv.w, O[d4 * 4 + 3]);
            }
        }
        __syncthreads();
    }

    // normalize + store
    float inv = 1.f / l;
    float* op = attn_out + ((size_t)(b * SEQ + row)) * DM + h * DK;
#pragma unroll
    for (int d = 0; d < DK; d += 4) {
        float4 o;
        o.x = O[d + 0] * inv;
        o.y = O[d + 1] * inv;
        o.z = O[d + 2] * inv;
        o.w = O[d + 3] * inv;
        *(float4*)&op[d] = o;
    }
}

// ---------------- launch ------------------------------------------------------
extern "C" void kernel_launch(void* const* d_in, const int* in_sizes, int n_in,
                              void* d_out, int out_size)
{
    const float* q  = (const float*)d_in[0];
    const float* k  = (const float*)d_in[1];
    const float* v  = (const float*)d_in[2];
    const float* Wq = (const float*)d_in[3];
    const float* bq = (const float*)d_in[4];
    const float* Wk = (const float*)d_in[5];
    const float* bk = (const float*)d_in[6];
    const float* Wv = (const float*)d_in[7];
    const float* bv = (const float*)d_in[8];
    const float* Wo = (const float*)d_in[9];
    const float* bo = (const float*)d_in[10];
    float* out = (float*)d_out;

    float* qproj; cudaGetSymbolAddress((void**)&qproj, g_qproj);
    float* kh;    cudaGetSymbolAddress((void**)&kh,    g_kh);
    float* vh;    cudaGetSymbolAddress((void**)&vh,    g_vh);
    float* attn;  cudaGetSymbolAddress((void**)&attn,  g_attn);

    // 1) Q projection: [8192,1024] @ [1024,1024] + bq
    {
        dim3 grid(DM / 128, BS / 128);
        sgemm_bias_kernel<128, 128, 16, 8, 8><<<grid, 256>>>(q, Wq, bq, qproj, BS, DM, DM);
    }
    // 2) K / V projections: [8192,1024] @ [1024,64] + b
    {
        dim3 grid(DK / 64, BS / 128);
        sgemm_bias_kernel<128, 64, 16, 8, 4><<<grid, 256>>>(k, Wk, bk, kh, BS, DK, DM);
        sgemm_bias_kernel<128, 64, 16, 8, 4><<<grid, 256>>>(v, Wv, bv, vh, BS, DK, DM);
    }
    // 3) MQA flash attention
    {
        dim3 grid(SEQ / BR, HEADS, BATCH);
        mqa_attn_kernel<<<grid, BR>>>(qproj, kh, vh, attn);
    }
    // 4) Output projection: [8192,1024] @ [1024,1024] + bo
    {
        dim3 grid(DM / 128, BS / 128);
        sgemm_bias_kernel<128, 128, 16, 8, 8><<<grid, 256>>>(attn, Wo, bo, out, BS, DM, DM);
    }
}